// round 1
// baseline (speedup 1.0000x reference)
#include <cuda_runtime.h>
#include <cstdint>

#define HID 1024
#define NEG_SLOPE 0.2f

static const int NMAX = 10240;
static const int EMAX = 163840;
#define TMAX (EMAX + NMAX)

// ---- scratch (static device globals; no allocations anywhere) ----
__device__ float g_xl[(size_t)NMAX * HID];
__device__ float g_xr[(size_t)NMAX * HID];
__device__ float g_h [(size_t)NMAX * HID];
__device__ float g_h1[(size_t)NMAX * 512];
__device__ float g_h2[(size_t)NMAX * 128];
__device__ float g_e [TMAX];
__device__ int   g_deg[NMAX];
__device__ int   g_cur[NMAX];
__device__ int   g_off[NMAX + 1];
__device__ int   g_csr[TMAX];

// ---- packed f32x2 helpers (Blackwell FFMA2 path) ----
__device__ __forceinline__ unsigned long long pack2(float x, float y) {
    unsigned long long r;
    asm("mov.b64 %0, {%1, %2};" : "=l"(r) : "f"(x), "f"(y));
    return r;
}
__device__ __forceinline__ float2 unpack2(unsigned long long v) {
    float2 r;
    asm("mov.b64 {%0, %1}, %2;" : "=f"(r.x), "=f"(r.y) : "l"(v));
    return r;
}
__device__ __forceinline__ void ffma2(unsigned long long& d,
                                      unsigned long long a,
                                      unsigned long long b) {
    asm("fma.rn.f32x2 %0, %1, %2, %0;" : "+l"(d) : "l"(a), "l"(b));
}

// ============================================================================
// SGEMM: C[M,N] = op(A[M,K] @ B[K,N] + bias), 64x64 tile, 256 thr, 4x4 micro
// ============================================================================
template <bool RELU>
__global__ __launch_bounds__(256, 2)
void sgemm_bias(const float* __restrict__ A, const float* __restrict__ B,
                const float* __restrict__ bias, float* __restrict__ C,
                int M, int Nn, int K)
{
    __shared__ __align__(16) float As[16][68];   // [kk][row], pad 68 for v4 reads
    __shared__ __align__(16) float Bs[16][64];   // [kk][col]

    const int tid = threadIdx.x;
    const int tx  = tid & 15;
    const int ty  = tid >> 4;
    const int row0 = blockIdx.y * 64;
    const int col0 = blockIdx.x * 64;

    unsigned long long acc[4][2];
#pragma unroll
    for (int i = 0; i < 4; i++) { acc[i][0] = 0ull; acc[i][1] = 0ull; }

    const int bkk = tid >> 4;
    const int bc4 = (tid & 15) * 4;

    for (int k0 = 0; k0 < K; k0 += 16) {
        // A tile: coalesced (kk-fast), transposed store into As[kk][row]
#pragma unroll
        for (int i = 0; i < 4; i++) {
            int idx = tid + i * 256;
            int kk  = idx & 15;
            int row = idx >> 4;
            int gr  = row0 + row;
            As[kk][row] = (gr < M) ? A[(size_t)gr * K + k0 + kk] : 0.f;
        }
        // B tile: one float4 span per thread, scalar-guarded for ragged N
        {
            const float* Bp = B + (size_t)(k0 + bkk) * Nn + col0 + bc4;
            float4 bv;
            bv.x = (col0 + bc4 + 0 < Nn) ? Bp[0] : 0.f;
            bv.y = (col0 + bc4 + 1 < Nn) ? Bp[1] : 0.f;
            bv.z = (col0 + bc4 + 2 < Nn) ? Bp[2] : 0.f;
            bv.w = (col0 + bc4 + 3 < Nn) ? Bp[3] : 0.f;
            *(float4*)&Bs[bkk][bc4] = bv;
        }
        __syncthreads();

#pragma unroll
        for (int kk = 0; kk < 16; kk++) {
            float4 a4 = *(const float4*)&As[kk][ty * 4];
            float4 b4 = *(const float4*)&Bs[kk][tx * 4];
            unsigned long long b01 = pack2(b4.x, b4.y);
            unsigned long long b23 = pack2(b4.z, b4.w);
            unsigned long long a0 = pack2(a4.x, a4.x);
            unsigned long long a1 = pack2(a4.y, a4.y);
            unsigned long long a2 = pack2(a4.z, a4.z);
            unsigned long long a3 = pack2(a4.w, a4.w);
            ffma2(acc[0][0], a0, b01); ffma2(acc[0][1], a0, b23);
            ffma2(acc[1][0], a1, b01); ffma2(acc[1][1], a1, b23);
            ffma2(acc[2][0], a2, b01); ffma2(acc[2][1], a2, b23);
            ffma2(acc[3][0], a3, b01); ffma2(acc[3][1], a3, b23);
        }
        __syncthreads();
    }

#pragma unroll
    for (int i = 0; i < 4; i++) {
        int r = row0 + ty * 4 + i;
        if (r >= M) continue;
        float2 p0 = unpack2(acc[i][0]);
        float2 p1 = unpack2(acc[i][1]);
        float v[4] = { p0.x, p0.y, p1.x, p1.y };
#pragma unroll
        for (int j = 0; j < 4; j++) {
            int c = col0 + tx * 4 + j;
            if (c < Nn) {
                float o = v[j] + bias[c];
                if (RELU) o = fmaxf(o, 0.f);
                C[(size_t)r * Nn + c] = o;
            }
        }
    }
}

// ============================================================================
// CSR build (dst-sorted incoming-edge lists; self-loops are k in [E, E+N))
// ============================================================================
__global__ void init_kernel(int n) {
    int i = blockIdx.x * blockDim.x + threadIdx.x;
    if (i < n) { g_deg[i] = 1; g_cur[i] = 0; }   // deg=1 accounts for self-loop
}

__global__ void count_kernel(const int* __restrict__ dst, int E) {
    int k = blockIdx.x * blockDim.x + threadIdx.x;
    if (k < E) atomicAdd(&g_deg[dst[k]], 1);
}

__global__ __launch_bounds__(1024)
void scan_kernel(int n) {
    __shared__ int part[1024];
    int tid = threadIdx.x;
    int chunk = (n + 1023) >> 10;
    int beg = tid * chunk;
    int end = min(beg + chunk, n);
    int s = 0;
    for (int i = beg; i < end; i++) s += g_deg[i];
    part[tid] = s;
    __syncthreads();
    for (int d = 1; d < 1024; d <<= 1) {
        int v = part[tid];
        int a = (tid >= d) ? part[tid - d] : 0;
        __syncthreads();
        part[tid] = v + a;
        __syncthreads();
    }
    int run = (tid > 0) ? part[tid - 1] : 0;
    for (int i = beg; i < end; i++) { g_off[i] = run; run += g_deg[i]; }
    if (tid == 1023) g_off[n] = part[1023];
}

__global__ void fill_kernel(const int* __restrict__ dst, int E, int total) {
    int k = blockIdx.x * blockDim.x + threadIdx.x;
    if (k >= total) return;
    int d = (k < E) ? dst[k] : (k - E);
    int pos = atomicAdd(&g_cur[d], 1);
    g_csr[g_off[d] + pos] = k;
}

// ============================================================================
// Edge scores: e[k] = att . LeakyReLU(xl[src] + xr[dst]); one warp per edge
// ============================================================================
__global__ __launch_bounds__(256)
void edge_e_kernel(const int* __restrict__ src, const int* __restrict__ dst,
                   const float* __restrict__ att, int E, int total)
{
    int w = blockIdx.x * 8 + (threadIdx.x >> 5);
    if (w >= total) return;
    int lane = threadIdx.x & 31;
    int s = (w < E) ? src[w] : (w - E);
    int d = (w < E) ? dst[w] : (w - E);
    const float4* xl4 = (const float4*)(g_xl + (size_t)s * HID);
    const float4* xr4 = (const float4*)(g_xr + (size_t)d * HID);
    const float4* at4 = (const float4*)att;
    float acc = 0.f;
#pragma unroll
    for (int j = 0; j < 8; j++) {
        int idx = lane + j * 32;
        float4 a = xl4[idx];
        float4 b = xr4[idx];
        float4 t = at4[idx];
        float v;
        v = a.x + b.x; v = (v > 0.f) ? v : NEG_SLOPE * v; acc = fmaf(v, t.x, acc);
        v = a.y + b.y; v = (v > 0.f) ? v : NEG_SLOPE * v; acc = fmaf(v, t.y, acc);
        v = a.z + b.z; v = (v > 0.f) ? v : NEG_SLOPE * v; acc = fmaf(v, t.z, acc);
        v = a.w + b.w; v = (v > 0.f) ? v : NEG_SLOPE * v; acc = fmaf(v, t.w, acc);
    }
#pragma unroll
    for (int o = 16; o > 0; o >>= 1) acc += __shfl_xor_sync(0xffffffffu, acc, o);
    if (lane == 0) g_e[w] = acc;
}

// ============================================================================
// Per-node segment softmax + weighted aggregation (no vector atomics).
// h[node] = relu(conv_b + sum_k alpha_k * xl[src_k]); block per node.
// ============================================================================
#define DEGCAP 1024
__global__ __launch_bounds__(256)
void aggregate_kernel(const int* __restrict__ src,
                      const float* __restrict__ conv_b, int E)
{
    int node = blockIdx.x;
    int tid = threadIdx.x;
    int beg = g_off[node];
    int deg = g_off[node + 1] - beg;

    __shared__ float s_w[DEGCAP];
    __shared__ int   s_src[DEGCAP];
    __shared__ float red[256];

    float m, ssum;
    float4 acc = make_float4(0.f, 0.f, 0.f, 0.f);

    if (deg <= DEGCAP) {
        for (int j = tid; j < deg; j += 256) {
            int k = g_csr[beg + j];
            s_w[j] = g_e[k];
            s_src[j] = (k < E) ? src[k] : (k - E);
        }
        __syncthreads();
        float mx = -1e30f;
        for (int j = tid; j < deg; j += 256) mx = fmaxf(mx, s_w[j]);
        red[tid] = mx; __syncthreads();
        for (int o = 128; o > 0; o >>= 1) {
            if (tid < o) red[tid] = fmaxf(red[tid], red[tid + o]);
            __syncthreads();
        }
        m = red[0];
        __syncthreads();
        for (int j = tid; j < deg; j += 256) s_w[j] = __expf(s_w[j] - m);
        float sl = 0.f;
        for (int j = tid; j < deg; j += 256) sl += s_w[j];
        red[tid] = sl; __syncthreads();
        for (int o = 128; o > 0; o >>= 1) {
            if (tid < o) red[tid] += red[tid + o];
            __syncthreads();
        }
        ssum = red[0];
        __syncthreads();
        for (int j = 0; j < deg; j++) {
            float wgt = s_w[j];
            const float4* row = (const float4*)(g_xl + (size_t)s_src[j] * HID);
            float4 v = row[tid];
            acc.x = fmaf(wgt, v.x, acc.x);
            acc.y = fmaf(wgt, v.y, acc.y);
            acc.z = fmaf(wgt, v.z, acc.z);
            acc.w = fmaf(wgt, v.w, acc.w);
        }
    } else {
        // gmem fallback (degree beyond cap; statistically never hit here)
        float mx = -1e30f;
        for (int j = tid; j < deg; j += 256) mx = fmaxf(mx, g_e[g_csr[beg + j]]);
        red[tid] = mx; __syncthreads();
        for (int o = 128; o > 0; o >>= 1) {
            if (tid < o) red[tid] = fmaxf(red[tid], red[tid + o]);
            __syncthreads();
        }
        m = red[0];
        __syncthreads();
        float sl = 0.f;
        for (int j = tid; j < deg; j += 256) sl += __expf(g_e[g_csr[beg + j]] - m);
        red[tid] = sl; __syncthreads();
        for (int o = 128; o > 0; o >>= 1) {
            if (tid < o) red[tid] += red[tid + o];
            __syncthreads();
        }
        ssum = red[0];
        __syncthreads();
        for (int j = 0; j < deg; j++) {
            int k = g_csr[beg + j];
            float wgt = __expf(g_e[k] - m);
            int sidx = (k < E) ? src[k] : (k - E);
            const float4* row = (const float4*)(g_xl + (size_t)sidx * HID);
            float4 v = row[tid];
            acc.x = fmaf(wgt, v.x, acc.x);
            acc.y = fmaf(wgt, v.y, acc.y);
            acc.z = fmaf(wgt, v.z, acc.z);
            acc.w = fmaf(wgt, v.w, acc.w);
        }
    }

    float inv = 1.f / ssum;
    float4 cb = ((const float4*)conv_b)[tid];
    float4 o;
    o.x = fmaxf(fmaf(acc.x, inv, cb.x), 0.f);
    o.y = fmaxf(fmaf(acc.y, inv, cb.y), 0.f);
    o.z = fmaxf(fmaf(acc.z, inv, cb.z), 0.f);
    o.w = fmaxf(fmaf(acc.w, inv, cb.w), 0.f);
    ((float4*)(g_h + (size_t)node * HID))[tid] = o;
}

// ============================================================================
// launch
// ============================================================================
extern "C" void kernel_launch(void* const* d_in, const int* in_sizes, int n_in,
                              void* d_out, int out_size)
{
    const float* x   = (const float*)d_in[0];
    const int*   ei  = (const int*)d_in[1];
    const float* Wl  = (const float*)d_in[2];
    const float* bl  = (const float*)d_in[3];
    const float* Wr  = (const float*)d_in[4];
    const float* br  = (const float*)d_in[5];
    const float* att = (const float*)d_in[6];
    const float* cb  = (const float*)d_in[7];
    const float* W1  = (const float*)d_in[8];
    const float* b1  = (const float*)d_in[9];
    const float* W2  = (const float*)d_in[10];
    const float* b2  = (const float*)d_in[11];
    const float* Wc  = (const float*)d_in[12];
    const float* bc  = (const float*)d_in[13];

    const int n = in_sizes[0] / 512;
    const int E = in_sizes[1] / 2;
    const int total = E + n;
    const int* srcA = ei;
    const int* dstA = ei + E;

    float *xl, *xr, *h, *h1, *h2;
    cudaGetSymbolAddress((void**)&xl, g_xl);
    cudaGetSymbolAddress((void**)&xr, g_xr);
    cudaGetSymbolAddress((void**)&h,  g_h);
    cudaGetSymbolAddress((void**)&h1, g_h1);
    cudaGetSymbolAddress((void**)&h2, g_h2);
    float* out = (float*)d_out;

    init_kernel<<<(n + 255) / 256, 256>>>(n);

    dim3 g1((1024 + 63) / 64, (n + 63) / 64);
    sgemm_bias<false><<<g1, 256>>>(x, Wl, bl, xl, n, 1024, 512);
    sgemm_bias<false><<<g1, 256>>>(x, Wr, br, xr, n, 1024, 512);

    count_kernel<<<(E + 255) / 256, 256>>>(dstA, E);
    scan_kernel<<<1, 1024>>>(n);
    fill_kernel<<<(total + 255) / 256, 256>>>(dstA, E, total);

    edge_e_kernel<<<(total + 7) / 8, 256>>>(srcA, dstA, att, E, total);
    aggregate_kernel<<<n, 256>>>(srcA, cb, E);

    dim3 g2((512 + 63) / 64, (n + 63) / 64);
    sgemm_bias<true><<<g2, 256>>>(h, W1, b1, h1, n, 512, 1024);
    dim3 g3((128 + 63) / 64, (n + 63) / 64);
    sgemm_bias<true><<<g3, 256>>>(h1, W2, b2, h2, n, 128, 512);
    dim3 g4((100 + 63) / 64, (n + 63) / 64);
    sgemm_bias<false><<<g4, 256>>>(h2, Wc, bc, out, n, 100, 128);
}

// round 4
// speedup vs baseline: 2.2360x; 2.2360x over previous
#include <cuda_runtime.h>
#include <cuda_bf16.h>
#include <cstdint>

#define HID 1024
#define NEG_SLOPE 0.2f

static const int NMAX = 10240;
static const int EMAX = 163840;
#define TMAX (EMAX + NMAX)

// ---------------- scratch (static device globals) ----------------
__device__ __align__(16) float g_xl[(size_t)NMAX * HID];
__device__ __align__(16) float g_xr[(size_t)NMAX * HID];
__device__ __align__(16) float g_e [TMAX];
__device__ int   g_deg[NMAX];
__device__ int   g_cur[NMAX];
__device__ int   g_off[NMAX + 1];
__device__ int   g_csr[TMAX];

// bf16 hi/lo split activations
__device__ __align__(16) __nv_bfloat16 g_xh [(size_t)NMAX * 512];
__device__ __align__(16) __nv_bfloat16 g_xlo[(size_t)NMAX * 512];
__device__ __align__(16) __nv_bfloat16 g_hh [(size_t)NMAX * HID];
__device__ __align__(16) __nv_bfloat16 g_hl [(size_t)NMAX * HID];
__device__ __align__(16) __nv_bfloat16 g_h1h[(size_t)NMAX * 512];
__device__ __align__(16) __nv_bfloat16 g_h1l[(size_t)NMAX * 512];
__device__ __align__(16) __nv_bfloat16 g_h2h[(size_t)NMAX * 128];
__device__ __align__(16) __nv_bfloat16 g_h2l[(size_t)NMAX * 128];

// transposed + split weights: Wt[n][k]
__device__ __align__(16) __nv_bfloat16 g_Wlt_h[1024 * 512], g_Wlt_l[1024 * 512];
__device__ __align__(16) __nv_bfloat16 g_Wrt_h[1024 * 512], g_Wrt_l[1024 * 512];
__device__ __align__(16) __nv_bfloat16 g_W1t_h[512 * 1024], g_W1t_l[512 * 1024];
__device__ __align__(16) __nv_bfloat16 g_W2t_h[128 * 512],  g_W2t_l[128 * 512];
__device__ __align__(16) __nv_bfloat16 g_Wct_h[112 * 128],  g_Wct_l[112 * 128];

// ---------------- PTX helpers (plain compute_103 ISA only) ----------------
__device__ __forceinline__ uint32_t smem_u32(const void* p) {
    uint32_t a;
    asm("{ .reg .u64 t; cvta.to.shared.u64 t, %1; cvt.u32.u64 %0, t; }"
        : "=r"(a) : "l"(p));
    return a;
}
__device__ __forceinline__ void cp16(uint32_t saddr, const void* gaddr, int srcsize) {
    asm volatile("cp.async.cg.shared.global [%0], [%1], 16, %2;"
                 :: "r"(saddr), "l"(gaddr), "r"(srcsize) : "memory");
}
#define CP_COMMIT() asm volatile("cp.async.commit_group;" ::: "memory")
#define CP_WAIT(n)  asm volatile("cp.async.wait_group %0;" :: "n"(n) : "memory")

__device__ __forceinline__ void ldsm4(uint32_t& r0, uint32_t& r1, uint32_t& r2,
                                      uint32_t& r3, uint32_t a) {
    asm volatile("ldmatrix.sync.aligned.m8n8.x4.shared.b16 {%0,%1,%2,%3}, [%4];"
                 : "=r"(r0), "=r"(r1), "=r"(r2), "=r"(r3) : "r"(a));
}
__device__ __forceinline__ void mma16816(float* d, const uint32_t* a,
                                         uint32_t b0, uint32_t b1) {
    asm volatile(
        "mma.sync.aligned.m16n8k16.row.col.f32.bf16.bf16.f32 "
        "{%0,%1,%2,%3}, {%4,%5,%6,%7}, {%8,%9}, {%0,%1,%2,%3};"
        : "+f"(d[0]), "+f"(d[1]), "+f"(d[2]), "+f"(d[3])
        : "r"(a[0]), "r"(a[1]), "r"(a[2]), "r"(a[3]), "r"(b0), "r"(b1));
}

// ============================================================================
// bf16-split GEMM on mma.sync: D[M,Nn] = act(A @ Wt^T + bias)
// A split (Ah,Al)[M][K], Wt split (Bh,Bl)[Nn][K], CTA tile 128x128, Kc=32,
// cp.async double-buffered. Tile layout: 128 rows x 64B, chunk' = c ^ ((r>>1)&3).
// ============================================================================
#define TILE_B   8192            // one 128x32 bf16 tile
#define STAGE_B  (4 * TILE_B)    // Ah, Al, Bh, Bl
#define GSMEM    (2 * STAGE_B)   // 64 KB

__device__ __forceinline__ void fill_tile_async(
    uint32_t dst, const __nv_bfloat16* __restrict__ src,
    int rowbase, int limit, int K, int k0, int tid)
{
    int fr = tid >> 2;
    int fc = tid & 3;
#pragma unroll
    for (int it = 0; it < 2; it++) {
        int row = fr + it * 64;
        int grow = rowbase + row;
        uint32_t saddr = dst + row * 64 + ((fc ^ ((row >> 1) & 3)) * 16);
        const void* g = src + (size_t)grow * K + k0 + fc * 8;
        cp16(saddr, g, (grow < limit) ? 16 : 0);
    }
}

template <bool RELU, bool WF32, bool WBF16>
__global__ __launch_bounds__(256, 1)
void gemm_mma(const __nv_bfloat16* __restrict__ Ah, const __nv_bfloat16* __restrict__ Al,
              const __nv_bfloat16* __restrict__ Bh, const __nv_bfloat16* __restrict__ Bl,
              const float* __restrict__ bias,
              float* __restrict__ C, __nv_bfloat16* __restrict__ Ch,
              __nv_bfloat16* __restrict__ Cl,
              int M, int Nn, int K)
{
    extern __shared__ char smem[];
    const uint32_t sb = smem_u32(smem);
    const int tid = threadIdx.x;
    const int wid = tid >> 5;
    const int lane = tid & 31;
    const int row0 = blockIdx.y * 128;
    const int col0 = blockIdx.x * 128;
    const int wm0 = (wid & 3) * 32;   // warp M offset (2 m16 tiles)
    const int wn0 = (wid >> 2) * 64;  // warp N offset (8 n8 tiles)

    float acc[2][8][4];
#pragma unroll
    for (int i = 0; i < 2; i++)
#pragma unroll
        for (int j = 0; j < 8; j++)
#pragma unroll
            for (int k = 0; k < 4; k++) acc[i][j][k] = 0.f;

    // per-thread ldmatrix in-tile offsets (loop invariant)
    uint32_t aoff[2][2], boff[4][2];
#pragma unroll
    for (int mt = 0; mt < 2; mt++) {
        int arow = wm0 + mt * 16 + (lane & 15);
        int hi = lane >> 4;                 // 0/1 -> k-half
#pragma unroll
        for (int s = 0; s < 2; s++) {
            int chunk = s * 2 + hi;
            aoff[mt][s] = arow * 64 + ((chunk ^ ((arow >> 1) & 3)) * 16);
        }
    }
#pragma unroll
    for (int bt = 0; bt < 4; bt++) {
        int brow = wn0 + bt * 16 + (lane & 7) + ((lane >> 4) & 1) * 8;
        int hi = (lane >> 3) & 1;
#pragma unroll
        for (int s = 0; s < 2; s++) {
            int chunk = s * 2 + hi;
            boff[bt][s] = brow * 64 + ((chunk ^ ((brow >> 1) & 3)) * 16);
        }
    }

    const int nC = K / 32;

    // prologue: stage 0 <- chunk 0
    {
        uint32_t st = sb;
        fill_tile_async(st + 0 * TILE_B, Ah, row0, M,  K, 0, tid);
        fill_tile_async(st + 1 * TILE_B, Al, row0, M,  K, 0, tid);
        fill_tile_async(st + 2 * TILE_B, Bh, col0, Nn, K, 0, tid);
        fill_tile_async(st + 3 * TILE_B, Bl, col0, Nn, K, 0, tid);
        CP_COMMIT();
    }

    for (int c = 0; c < nC; c++) {
        const uint32_t st = sb + (c & 1) * STAGE_B;
        if (c + 1 < nC) {
            uint32_t nx = sb + ((c + 1) & 1) * STAGE_B;
            int k0 = (c + 1) * 32;
            fill_tile_async(nx + 0 * TILE_B, Ah, row0, M,  K, k0, tid);
            fill_tile_async(nx + 1 * TILE_B, Al, row0, M,  K, k0, tid);
            fill_tile_async(nx + 2 * TILE_B, Bh, col0, Nn, K, k0, tid);
            fill_tile_async(nx + 3 * TILE_B, Bl, col0, Nn, K, k0, tid);
            CP_COMMIT();
            CP_WAIT(1);
        } else {
            CP_WAIT(0);
        }
        __syncthreads();

#pragma unroll
        for (int s = 0; s < 2; s++) {
            uint32_t ah[2][4], al[2][4], bh[4][4], bl[4][4];
#pragma unroll
            for (int mt = 0; mt < 2; mt++) {
                ldsm4(ah[mt][0], ah[mt][1], ah[mt][2], ah[mt][3],
                      st + 0 * TILE_B + aoff[mt][s]);
                ldsm4(al[mt][0], al[mt][1], al[mt][2], al[mt][3],
                      st + 1 * TILE_B + aoff[mt][s]);
            }
#pragma unroll
            for (int bt = 0; bt < 4; bt++) {
                ldsm4(bh[bt][0], bh[bt][1], bh[bt][2], bh[bt][3],
                      st + 2 * TILE_B + boff[bt][s]);
                ldsm4(bl[bt][0], bl[bt][1], bl[bt][2], bl[bt][3],
                      st + 3 * TILE_B + boff[bt][s]);
            }
#pragma unroll
            for (int mt = 0; mt < 2; mt++) {
#pragma unroll
                for (int bt = 0; bt < 4; bt++) {
                    mma16816(acc[mt][2 * bt + 0], ah[mt], bh[bt][0], bh[bt][1]);
                    mma16816(acc[mt][2 * bt + 1], ah[mt], bh[bt][2], bh[bt][3]);
                    mma16816(acc[mt][2 * bt + 0], ah[mt], bl[bt][0], bl[bt][1]);
                    mma16816(acc[mt][2 * bt + 1], ah[mt], bl[bt][2], bl[bt][3]);
                    mma16816(acc[mt][2 * bt + 0], al[mt], bh[bt][0], bh[bt][1]);
                    mma16816(acc[mt][2 * bt + 1], al[mt], bh[bt][2], bh[bt][3]);
                }
            }
        }
        __syncthreads();
    }

    // epilogue straight from fragments
#pragma unroll
    for (int mt = 0; mt < 2; mt++) {
#pragma unroll
        for (int nt = 0; nt < 8; nt++) {
            int col = col0 + wn0 + nt * 8 + (lane & 3) * 2;
            if (col >= Nn) continue;
            float bx = bias[col], by = bias[col + 1];
#pragma unroll
            for (int half = 0; half < 2; half++) {
                int grow = row0 + wm0 + mt * 16 + (lane >> 2) + half * 8;
                if (grow >= M) continue;
                float ox = acc[mt][nt][half * 2 + 0] + bx;
                float oy = acc[mt][nt][half * 2 + 1] + by;
                if (RELU) { ox = fmaxf(ox, 0.f); oy = fmaxf(oy, 0.f); }
                size_t idx = (size_t)grow * Nn + col;
                if (WF32) {
                    *(float2*)(C + idx) = make_float2(ox, oy);
                }
                if (WBF16) {
                    __nv_bfloat16 hx = __float2bfloat16(ox);
                    __nv_bfloat16 hy = __float2bfloat16(oy);
                    *(__nv_bfloat162*)(Ch + idx) = __nv_bfloat162(hx, hy);
                    *(__nv_bfloat162*)(Cl + idx) = __floats2bfloat162_rn(
                        ox - __bfloat162float(hx), oy - __bfloat162float(hy));
                }
            }
        }
    }
}

// ============================================================================
// Conversions
// ============================================================================
__global__ void split_x_kernel(const float4* __restrict__ src,
                               __nv_bfloat162* __restrict__ h2,
                               __nv_bfloat162* __restrict__ l2, int n4)
{
    int i = blockIdx.x * blockDim.x + threadIdx.x;
    if (i >= n4) return;
    float4 v = src[i];
    __nv_bfloat16 hx = __float2bfloat16(v.x), hy = __float2bfloat16(v.y);
    __nv_bfloat16 hz = __float2bfloat16(v.z), hw = __float2bfloat16(v.w);
    h2[i * 2 + 0] = __floats2bfloat162_rn(v.x, v.y);
    h2[i * 2 + 1] = __floats2bfloat162_rn(v.z, v.w);
    l2[i * 2 + 0] = __floats2bfloat162_rn(v.x - __bfloat162float(hx), v.y - __bfloat162float(hy));
    l2[i * 2 + 1] = __floats2bfloat162_rn(v.z - __bfloat162float(hz), v.w - __bfloat162float(hw));
}

__global__ void tsplit_kernel(const float* __restrict__ W,
                              __nv_bfloat16* __restrict__ th, __nv_bfloat16* __restrict__ tl,
                              int K, int N)
{
    __shared__ float t[32][33];
    int k0 = blockIdx.y * 32, n0 = blockIdx.x * 32;
    int tx = threadIdx.x, ty = threadIdx.y;
#pragma unroll
    for (int i = 0; i < 4; i++) {
        int k = k0 + ty + i * 8;
        t[ty + i * 8][tx] = (k < K && n0 + tx < N) ? W[(size_t)k * N + n0 + tx] : 0.f;
    }
    __syncthreads();
#pragma unroll
    for (int i = 0; i < 4; i++) {
        int n = n0 + ty + i * 8;
        int k = k0 + tx;
        if (n < N && k < K) {
            float v = t[tx][ty + i * 8];
            __nv_bfloat16 hb = __float2bfloat16(v);
            th[(size_t)n * K + k] = hb;
            tl[(size_t)n * K + k] = __float2bfloat16(v - __bfloat162float(hb));
        }
    }
}

// ============================================================================
// CSR build
// ============================================================================
__global__ void init_kernel(int n) {
    int i = blockIdx.x * blockDim.x + threadIdx.x;
    if (i < n) { g_deg[i] = 1; g_cur[i] = 0; }
}
__global__ void count_kernel(const int* __restrict__ dst, int E) {
    int k = blockIdx.x * blockDim.x + threadIdx.x;
    if (k < E) atomicAdd(&g_deg[dst[k]], 1);
}
__global__ __launch_bounds__(1024)
void scan_kernel(int n) {
    __shared__ int part[1024];
    int tid = threadIdx.x;
    int chunk = (n + 1023) >> 10;
    int beg = tid * chunk;
    int end = min(beg + chunk, n);
    int s = 0;
    for (int i = beg; i < end; i++) s += g_deg[i];
    part[tid] = s;
    __syncthreads();
    for (int d = 1; d < 1024; d <<= 1) {
        int v = part[tid];
        int a = (tid >= d) ? part[tid - d] : 0;
        __syncthreads();
        part[tid] = v + a;
        __syncthreads();
    }
    int run = (tid > 0) ? part[tid - 1] : 0;
    for (int i = beg; i < end; i++) { g_off[i] = run; run += g_deg[i]; }
    if (tid == 1023) g_off[n] = part[1023];
}
__global__ void fill_kernel(const int* __restrict__ dst, int E, int total) {
    int k = blockIdx.x * blockDim.x + threadIdx.x;
    if (k >= total) return;
    int d = (k < E) ? dst[k] : (k - E);
    int pos = atomicAdd(&g_cur[d], 1);
    g_csr[g_off[d] + pos] = k;
}

// ============================================================================
// Edge scores
// ============================================================================
__global__ __launch_bounds__(256)
void edge_e_kernel(const int* __restrict__ src, const int* __restrict__ dst,
                   const float* __restrict__ att, int E, int total)
{
    int w = blockIdx.x * 8 + (threadIdx.x >> 5);
    if (w >= total) return;
    int lane = threadIdx.x & 31;
    int s = (w < E) ? src[w] : (w - E);
    int d = (w < E) ? dst[w] : (w - E);
    const float4* xl4 = (const float4*)(g_xl + (size_t)s * HID);
    const float4* xr4 = (const float4*)(g_xr + (size_t)d * HID);
    const float4* at4 = (const float4*)att;
    float acc = 0.f;
#pragma unroll
    for (int j = 0; j < 8; j++) {
        int idx = lane + j * 32;
        float4 a = xl4[idx];
        float4 b = xr4[idx];
        float4 t = at4[idx];
        float v;
        v = a.x + b.x; v = (v > 0.f) ? v : NEG_SLOPE * v; acc = fmaf(v, t.x, acc);
        v = a.y + b.y; v = (v > 0.f) ? v : NEG_SLOPE * v; acc = fmaf(v, t.y, acc);
        v = a.z + b.z; v = (v > 0.f) ? v : NEG_SLOPE * v; acc = fmaf(v, t.z, acc);
        v = a.w + b.w; v = (v > 0.f) ? v : NEG_SLOPE * v; acc = fmaf(v, t.w, acc);
    }
#pragma unroll
    for (int o = 16; o > 0; o >>= 1) acc += __shfl_xor_sync(0xffffffffu, acc, o);
    if (lane == 0) g_e[w] = acc;
}

// ============================================================================
// Segment softmax + aggregation; writes bf16 hi/lo of relu(h)
// ============================================================================
#define DEGCAP 1024
__global__ __launch_bounds__(256)
void aggregate_kernel(const int* __restrict__ src,
                      const float* __restrict__ conv_b, int E)
{
    int node = blockIdx.x;
    int tid = threadIdx.x;
    int beg = g_off[node];
    int deg = g_off[node + 1] - beg;

    __shared__ float s_w[DEGCAP];
    __shared__ int   s_src[DEGCAP];
    __shared__ float red[256];

    float m, ssum;
    float4 acc = make_float4(0.f, 0.f, 0.f, 0.f);

    if (deg <= DEGCAP) {
        for (int j = tid; j < deg; j += 256) {
            int k = g_csr[beg + j];
            s_w[j] = g_e[k];
            s_src[j] = (k < E) ? src[k] : (k - E);
        }
        __syncthreads();
        float mx = -1e30f;
        for (int j = tid; j < deg; j += 256) mx = fmaxf(mx, s_w[j]);
        red[tid] = mx; __syncthreads();
        for (int o = 128; o > 0; o >>= 1) {
            if (tid < o) red[tid] = fmaxf(red[tid], red[tid + o]);
            __syncthreads();
        }
        m = red[0];
        __syncthreads();
        for (int j = tid; j < deg; j += 256) s_w[j] = __expf(s_w[j] - m);
        float sl = 0.f;
        for (int j = tid; j < deg; j += 256) sl += s_w[j];
        red[tid] = sl; __syncthreads();
        for (int o = 128; o > 0; o >>= 1) {
            if (tid < o) red[tid] += red[tid + o];
            __syncthreads();
        }
        ssum = red[0];
        __syncthreads();
        for (int j = 0; j < deg; j++) {
            float wgt = s_w[j];
            const float4* row = (const float4*)(g_xl + (size_t)s_src[j] * HID);
            float4 v = row[tid];
            acc.x = fmaf(wgt, v.x, acc.x);
            acc.y = fmaf(wgt, v.y, acc.y);
            acc.z = fmaf(wgt, v.z, acc.z);
            acc.w = fmaf(wgt, v.w, acc.w);
        }
    } else {
        float mx = -1e30f;
        for (int j = tid; j < deg; j += 256) mx = fmaxf(mx, g_e[g_csr[beg + j]]);
        red[tid] = mx; __syncthreads();
        for (int o = 128; o > 0; o >>= 1) {
            if (tid < o) red[tid] = fmaxf(red[tid], red[tid + o]);
            __syncthreads();
        }
        m = red[0];
        __syncthreads();
        float sl = 0.f;
        for (int j = tid; j < deg; j += 256) sl += __expf(g_e[g_csr[beg + j]] - m);
        red[tid] = sl; __syncthreads();
        for (int o = 128; o > 0; o >>= 1) {
            if (tid < o) red[tid] += red[tid + o];
            __syncthreads();
        }
        ssum = red[0];
        __syncthreads();
        for (int j = 0; j < deg; j++) {
            int k = g_csr[beg + j];
            float wgt = __expf(g_e[k] - m);
            int sidx = (k < E) ? src[k] : (k - E);
            const float4* row = (const float4*)(g_xl + (size_t)sidx * HID);
            float4 v = row[tid];
            acc.x = fmaf(wgt, v.x, acc.x);
            acc.y = fmaf(wgt, v.y, acc.y);
            acc.z = fmaf(wgt, v.z, acc.z);
            acc.w = fmaf(wgt, v.w, acc.w);
        }
    }

    float inv = 1.f / ssum;
    float4 cb = ((const float4*)conv_b)[tid];
    float4 o;
    o.x = fmaxf(fmaf(acc.x, inv, cb.x), 0.f);
    o.y = fmaxf(fmaf(acc.y, inv, cb.y), 0.f);
    o.z = fmaxf(fmaf(acc.z, inv, cb.z), 0.f);
    o.w = fmaxf(fmaf(acc.w, inv, cb.w), 0.f);

    size_t base = (size_t)node * HID + tid * 4;
    __nv_bfloat16 hx = __float2bfloat16(o.x), hy = __float2bfloat16(o.y);
    __nv_bfloat16 hz = __float2bfloat16(o.z), hw = __float2bfloat16(o.w);
    __nv_bfloat162* hh2 = (__nv_bfloat162*)(g_hh + base);
    __nv_bfloat162* hl2 = (__nv_bfloat162*)(g_hl + base);
    hh2[0] = __floats2bfloat162_rn(o.x, o.y);
    hh2[1] = __floats2bfloat162_rn(o.z, o.w);
    hl2[0] = __floats2bfloat162_rn(o.x - __bfloat162float(hx), o.y - __bfloat162float(hy));
    hl2[1] = __floats2bfloat162_rn(o.z - __bfloat162float(hz), o.w - __bfloat162float(hw));
}

// ============================================================================
// launch
// ============================================================================
extern "C" void kernel_launch(void* const* d_in, const int* in_sizes, int n_in,
                              void* d_out, int out_size)
{
    const float* x   = (const float*)d_in[0];
    const int*   ei  = (const int*)d_in[1];
    const float* Wl  = (const float*)d_in[2];
    const float* bl  = (const float*)d_in[3];
    const float* Wr  = (const float*)d_in[4];
    const float* br  = (const float*)d_in[5];
    const float* att = (const float*)d_in[6];
    const float* cb  = (const float*)d_in[7];
    const float* W1  = (const float*)d_in[8];
    const float* b1  = (const float*)d_in[9];
    const float* W2  = (const float*)d_in[10];
    const float* b2  = (const float*)d_in[11];
    const float* Wc  = (const float*)d_in[12];
    const float* bc  = (const float*)d_in[13];

    const int n = in_sizes[0] / 512;
    const int E = in_sizes[1] / 2;
    const int total = E + n;
    const int* srcA = ei;
    const int* dstA = ei + E;

    float *xl, *xr;
    __nv_bfloat16 *xh, *xlo, *hh, *hl, *h1h, *h1l, *h2h, *h2l;
    __nv_bfloat16 *Wlt_h, *Wlt_l, *Wrt_h, *Wrt_l, *W1t_h, *W1t_l, *W2t_h, *W2t_l, *Wct_h, *Wct_l;
    cudaGetSymbolAddress((void**)&xl,  g_xl);
    cudaGetSymbolAddress((void**)&xr,  g_xr);
    cudaGetSymbolAddress((void**)&xh,  g_xh);
    cudaGetSymbolAddress((void**)&xlo, g_xlo);
    cudaGetSymbolAddress((void**)&hh,  g_hh);
    cudaGetSymbolAddress((void**)&hl,  g_hl);
    cudaGetSymbolAddress((void**)&h1h, g_h1h);
    cudaGetSymbolAddress((void**)&h1l, g_h1l);
    cudaGetSymbolAddress((void**)&h2h, g_h2h);
    cudaGetSymbolAddress((void**)&h2l, g_h2l);
    cudaGetSymbolAddress((void**)&Wlt_h, g_Wlt_h);
    cudaGetSymbolAddress((void**)&Wlt_l, g_Wlt_l);
    cudaGetSymbolAddress((void**)&Wrt_h, g_Wrt_h);
    cudaGetSymbolAddress((void**)&Wrt_l, g_Wrt_l);
    cudaGetSymbolAddress((void**)&W1t_h, g_W1t_h);
    cudaGetSymbolAddress((void**)&W1t_l, g_W1t_l);
    cudaGetSymbolAddress((void**)&W2t_h, g_W2t_h);
    cudaGetSymbolAddress((void**)&W2t_l, g_W2t_l);
    cudaGetSymbolAddress((void**)&Wct_h, g_Wct_h);
    cudaGetSymbolAddress((void**)&Wct_l, g_Wct_l);
    float* out = (float*)d_out;

    cudaFuncSetAttribute(gemm_mma<false, true, false>,
                         cudaFuncAttributeMaxDynamicSharedMemorySize, GSMEM);
    cudaFuncSetAttribute(gemm_mma<true, false, true>,
                         cudaFuncAttributeMaxDynamicSharedMemorySize, GSMEM);

    // conversions
    int n4 = n * 512 / 4;
    split_x_kernel<<<(n4 + 255) / 256, 256>>>((const float4*)x,
                                              (__nv_bfloat162*)xh, (__nv_bfloat162*)xlo, n4);
    dim3 tb(32, 8);
    tsplit_kernel<<<dim3(1024 / 32, 512 / 32), tb>>>(Wl, Wlt_h, Wlt_l, 512, 1024);
    tsplit_kernel<<<dim3(1024 / 32, 512 / 32), tb>>>(Wr, Wrt_h, Wrt_l, 512, 1024);
    tsplit_kernel<<<dim3(512 / 32, 1024 / 32), tb>>>(W1, W1t_h, W1t_l, 1024, 512);
    tsplit_kernel<<<dim3(128 / 32, 512 / 32), tb>>>(W2, W2t_h, W2t_l, 512, 128);
    tsplit_kernel<<<dim3(4, 4), tb>>>(Wc, Wct_h, Wct_l, 128, 100);

    init_kernel<<<(n + 255) / 256, 256>>>(n);

    // xl / xr transforms (fp32 out, no relu)
    dim3 gx(1024 / 128, (n + 127) / 128);
    gemm_mma<false, true, false><<<gx, 256, GSMEM>>>(xh, xlo, Wlt_h, Wlt_l, bl,
                                                     xl, nullptr, nullptr, n, 1024, 512);
    gemm_mma<false, true, false><<<gx, 256, GSMEM>>>(xh, xlo, Wrt_h, Wrt_l, br,
                                                     xr, nullptr, nullptr, n, 1024, 512);

    count_kernel<<<(E + 255) / 256, 256>>>(dstA, E);
    scan_kernel<<<1, 1024>>>(n);
    fill_kernel<<<(total + 255) / 256, 256>>>(dstA, E, total);

    edge_e_kernel<<<(total + 7) / 8, 256>>>(srcA, dstA, att, E, total);
    aggregate_kernel<<<n, 256>>>(srcA, cb, E);

    // MLP head
    dim3 g1(512 / 128, (n + 127) / 128);
    gemm_mma<true, false, true><<<g1, 256, GSMEM>>>(hh, hl, W1t_h, W1t_l, b1,
                                                    nullptr, h1h, h1l, n, 512, 1024);
    dim3 g2(1, (n + 127) / 128);
    gemm_mma<true, false, true><<<g2, 256, GSMEM>>>(h1h, h1l, W2t_h, W2t_l, b2,
                                                    nullptr, h2h, h2l, n, 128, 512);
    dim3 g3(1, (n + 127) / 128);
    gemm_mma<false, true, false><<<g3, 256, GSMEM>>>(h2h, h2l, Wct_h, Wct_l, bc,
                                                     out, nullptr, nullptr, n, 100, 128);
}